// round 1
// baseline (speedup 1.0000x reference)
#include <cuda_runtime.h>

// WinCorr: corr[b,off,z,y,x] = (1/8) * sum_c x[b,c,z,y,x] * y[b,c,z+dz-1,y+dy-1,x+dx-1]
// Shapes: x,y = (2,64,80,80,80) f32 ; out = (2,27,80,80,80) f32
// off = dz*9 + dy*3 + dx, dz/dy/dx in [0,3)

#define B_  2
#define C_  64
#define D_  80
#define H_  80
#define W_  80

#define TZ  4
#define TY  8
#define TXB 16      // x extent per block
#define TX  4       // x outputs per thread
#define NTH (TZ*TY*(TXB/TX))   // 128 threads

#define SMZ (TZ+2)  // 6
#define SMY (TY+2)  // 10
#define SMXV (TXB+2) // 18 valid columns
#define SMX 20       // padded stride (floats) -> 16B-aligned float4 rows

__global__ void __launch_bounds__(NTH)
wincorr_kernel(const float* __restrict__ x,
               const float* __restrict__ y,
               float* __restrict__ out)
{
    // ---- decode block -> (b, z0, y0, x0) ----
    int bid = blockIdx.x;
    int bx = bid % (W_ / TXB); bid /= (W_ / TXB);   // 5
    int by = bid % (H_ / TY);  bid /= (H_ / TY);    // 10
    int bz = bid % (D_ / TZ);  bid /= (D_ / TZ);    // 20
    int b  = bid;                                   // 0..1
    const int z0 = bz * TZ, y0 = by * TY, x0 = bx * TXB;

    const int tid = threadIdx.x;
    const int tx = tid & 3;          // 0..3  (x-chunk)
    const int ty = (tid >> 2) & 7;   // 0..7
    const int tz = tid >> 5;         // 0..3

    __shared__ float sm[SMZ][SMY][SMX];

    float acc[27][TX];
#pragma unroll
    for (int o = 0; o < 27; o++)
#pragma unroll
        for (int i = 0; i < TX; i++) acc[o][i] = 0.f;

    const long plane = (long)H_ * W_;       // 6400
    const long vol   = (long)D_ * plane;    // 512000
    const float* xb = x + (long)b * C_ * vol;
    const float* yb = y + (long)b * C_ * vol;

    // per-thread x pointer offset (constant across channels)
    const long x_off = (long)(z0 + tz) * plane + (long)(y0 + ty) * W_ + (x0 + tx * TX);

    for (int c = 0; c < C_; c++) {
        const float* yc = yb + (long)c * vol;

        __syncthreads();   // protect previous tile reads
        // ---- stage y halo tile (6 x 10 x 18) ----
        for (int i = tid; i < SMZ * SMY * SMXV; i += NTH) {
            int lx = i % SMXV;
            int t  = i / SMXV;
            int ly = t % SMY;
            int lz = t / SMY;
            int gz = z0 - 1 + lz;
            int gy = y0 - 1 + ly;
            int gx = x0 - 1 + lx;
            float v = 0.f;
            if ((unsigned)gz < (unsigned)D_ &&
                (unsigned)gy < (unsigned)H_ &&
                (unsigned)gx < (unsigned)W_)
                v = yc[(long)gz * plane + gy * W_ + gx];
            sm[lz][ly][lx] = v;
        }
        __syncthreads();

        // ---- x values for this channel (vector load) ----
        const float4 xv = *(const float4*)(xb + (long)c * vol + x_off);
        const float xa[TX] = { xv.x, xv.y, xv.z, xv.w };

        // ---- accumulate 27 offsets over TX outputs ----
#pragma unroll
        for (int dz = 0; dz < 3; dz++) {
#pragma unroll
            for (int dy = 0; dy < 3; dy++) {
                const float* row = &sm[tz + dz][ty + dy][tx * TX];
                const float4 m = *(const float4*)row;   // 16B-aligned (stride 20 fl, tx*4)
                const float l0 = m.x, l1 = m.y, l2 = m.z, l3 = m.w;
                const float l4 = row[4];
                const float l5 = row[5];
                const float l[6] = { l0, l1, l2, l3, l4, l5 };
                const int ob = dz * 9 + dy * 3;
#pragma unroll
                for (int dx = 0; dx < 3; dx++) {
#pragma unroll
                    for (int i = 0; i < TX; i++)
                        acc[ob + dx][i] = fmaf(xa[i], l[i + dx], acc[ob + dx][i]);
                }
            }
        }
    }

    // ---- write out: out[b][off][z][y][x], scale = 64^{-1/2} = 0.125 ----
    const float scale = 0.125f;
    const long sp = (long)(z0 + tz) * plane + (long)(y0 + ty) * W_ + (x0 + tx * TX);
#pragma unroll
    for (int off = 0; off < 27; off++) {
        float4 o;
        o.x = acc[off][0] * scale;
        o.y = acc[off][1] * scale;
        o.z = acc[off][2] * scale;
        o.w = acc[off][3] * scale;
        *(float4*)(out + ((long)b * 27 + off) * vol + sp) = o;
    }
}

extern "C" void kernel_launch(void* const* d_in, const int* in_sizes, int n_in,
                              void* d_out, int out_size)
{
    const float* x = (const float*)d_in[0];
    const float* y = (const float*)d_in[1];
    float* out = (float*)d_out;

    const int nblocks = B_ * (D_ / TZ) * (H_ / TY) * (W_ / TXB); // 2*20*10*5 = 2000
    wincorr_kernel<<<nblocks, NTH>>>(x, y, out);
}

// round 2
// speedup vs baseline: 2.2679x; 2.2679x over previous
#include <cuda_runtime.h>
#include <cstdint>

// WinCorr: corr[b,off,z,y,x] = (1/8) * sum_c x[b,c,z,y,x] * y[b,c,z+dz-1,y+dy-1,x+dx-1]
// x,y = (2,64,80,80,80) f32 ; out = (2,27,80,80,80) f32

#define B_  2
#define C_  64
#define D_  80
#define H_  80
#define W_  80

#define TZ  4
#define TY  8
#define TXB 16
#define TX  4
#define NTH 128

#define SMZ 6
#define SMY 10
#define SMXV 18      // valid columns
#define SMX 20       // padded stride (floats), 16B-aligned rows
#define NSTAGE (SMZ*SMY*SMXV)          // 1080
#define BUFBYTES (SMZ*SMY*SMX*4)       // 4800

__device__ __forceinline__ uint32_t smem_u32(const void* p) {
    return (uint32_t)__cvta_generic_to_shared(p);
}
__device__ __forceinline__ void cp_async4(uint32_t saddr, const void* gaddr, uint32_t srcsz) {
    asm volatile("cp.async.ca.shared.global [%0], [%1], 4, %2;\n"
                 :: "r"(saddr), "l"(gaddr), "r"(srcsz) : "memory");
}
__device__ __forceinline__ void cp_commit() {
    asm volatile("cp.async.commit_group;\n" ::: "memory");
}
template<int N> __device__ __forceinline__ void cp_wait() {
    asm volatile("cp.async.wait_group %0;\n" :: "n"(N) : "memory");
}

__global__ void __launch_bounds__(NTH)
wincorr_kernel(const float* __restrict__ x,
               const float* __restrict__ y,
               float* __restrict__ out)
{
    // ---- decode block -> (b, z0, y0, x0) ----
    int bid = blockIdx.x;
    int bx = bid % (W_ / TXB); bid /= (W_ / TXB);
    int by = bid % (H_ / TY);  bid /= (H_ / TY);
    int bz = bid % (D_ / TZ);  bid /= (D_ / TZ);
    int b  = bid;
    const int z0 = bz * TZ, y0 = by * TY, x0 = bx * TXB;

    const int tid = threadIdx.x;
    const int tx = tid & 3;
    const int ty = (tid >> 2) & 7;
    const int tz = tid >> 5;

    __shared__ float sm[2][SMZ][SMY][SMX];

    const int plane = H_ * W_;        // 6400
    const int vol   = D_ * plane;     // 512000
    const uint32_t volbytes = (uint32_t)vol * 4u;

    const float* xb = x + (size_t)b * C_ * vol;
    const float* yb = y + (size_t)b * C_ * vol;
    const char*  ybc = (const char*)yb;

    // ---- precompute staging slots (channel-invariant) ----
    uint32_t sadr[9];   // smem byte address (buffer 0)
    uint32_t goff[9];   // byte offset into yb for c=0 (clamped in-bounds)
    uint32_t ssz[9];    // 4 if in-bounds else 0 (zfill)
    bool     sval[9];
#pragma unroll
    for (int k = 0; k < 9; k++) {
        int i = tid + k * NTH;
        sval[k] = (i < NSTAGE);
        int ii = sval[k] ? i : 0;
        int lx = ii % SMXV;
        int t  = ii / SMXV;
        int ly = t % SMY;
        int lz = t / SMY;
        int gz = z0 - 1 + lz, gy = y0 - 1 + ly, gx = x0 - 1 + lx;
        bool inb = ((unsigned)gz < (unsigned)D_) &&
                   ((unsigned)gy < (unsigned)H_) &&
                   ((unsigned)gx < (unsigned)W_);
        int cz = min(max(gz, 0), D_ - 1);
        int cy = min(max(gy, 0), H_ - 1);
        int cx = min(max(gx, 0), W_ - 1);
        goff[k] = (uint32_t)((cz * plane + cy * W_ + cx) * 4);
        ssz[k]  = inb ? 4u : 0u;
        sadr[k] = smem_u32(&sm[0][lz][ly][lx]);
    }

    float acc[27][TX];
#pragma unroll
    for (int o = 0; o < 27; o++)
#pragma unroll
        for (int i = 0; i < TX; i++) acc[o][i] = 0.f;

    const float* xp = xb + (size_t)(z0 + tz) * plane + (y0 + ty) * W_ + x0 + tx * TX;

    // ---- prologue: stage c=0 into buffer 0, prefetch x[0] ----
#pragma unroll
    for (int k = 0; k < 9; k++)
        if (sval[k]) cp_async4(sadr[k], ybc + goff[k], ssz[k]);
    cp_commit();

    float4 xv = *(const float4*)xp;

    for (int c = 0; c < C_; c++) {
        // stage channel c+1 into the other buffer (safe: sync at end of prev iter)
        if (c + 1 < C_) {
            const uint32_t cb = (uint32_t)(c + 1) * volbytes;
            const uint32_t bo = (uint32_t)((c + 1) & 1) * BUFBYTES;
#pragma unroll
            for (int k = 0; k < 9; k++)
                if (sval[k]) cp_async4(sadr[k] + bo, ybc + (goff[k] + cb), ssz[k]);
            cp_commit();
            cp_wait<1>();    // channel c's buffer is complete
        } else {
            cp_wait<0>();
        }
        __syncthreads();     // make all threads' cp.async data visible

        // prefetch x for c+1 (latency hidden under the 108 FMAs below)
        float4 xnext;
        if (c + 1 < C_) xnext = *(const float4*)(xp + (size_t)(c + 1) * vol);

        const float xa[TX] = { xv.x, xv.y, xv.z, xv.w };
        const float (*smb)[SMY][SMX] = sm[c & 1];

#pragma unroll
        for (int dz = 0; dz < 3; dz++) {
#pragma unroll
            for (int dy = 0; dy < 3; dy++) {
                const float* row = &smb[tz + dz][ty + dy][tx * TX];
                const float4 m  = *(const float4*)row;          // 16B aligned
                const float2 m2 = *(const float2*)(row + 4);    // 8B aligned
                const float l[6] = { m.x, m.y, m.z, m.w, m2.x, m2.y };
                const int ob = dz * 9 + dy * 3;
#pragma unroll
                for (int dx = 0; dx < 3; dx++)
#pragma unroll
                    for (int i = 0; i < TX; i++)
                        acc[ob + dx][i] = fmaf(xa[i], l[i + dx], acc[ob + dx][i]);
            }
        }

        if (c + 1 < C_) xv = xnext;
        __syncthreads();     // protect buffer (c+2)&1 overwrite next iter
    }

    // ---- write out with streaming hint (don't pollute L2) ----
    const float scale = 0.125f;
    const size_t sp = (size_t)(z0 + tz) * plane + (size_t)(y0 + ty) * W_ + (x0 + tx * TX);
    float* outb = out + (size_t)b * 27 * vol + sp;
#pragma unroll
    for (int off = 0; off < 27; off++) {
        float4 o;
        o.x = acc[off][0] * scale;
        o.y = acc[off][1] * scale;
        o.z = acc[off][2] * scale;
        o.w = acc[off][3] * scale;
        __stcs((float4*)(outb + (size_t)off * vol), o);
    }
}

extern "C" void kernel_launch(void* const* d_in, const int* in_sizes, int n_in,
                              void* d_out, int out_size)
{
    const float* x = (const float*)d_in[0];
    const float* y = (const float*)d_in[1];
    float* out = (float*)d_out;

    const int nblocks = B_ * (D_ / TZ) * (H_ / TY) * (W_ / TXB); // 2000
    wincorr_kernel<<<nblocks, NTH>>>(x, y, out);
}

// round 3
// speedup vs baseline: 2.2946x; 1.0118x over previous
#include <cuda_runtime.h>
#include <cstdint>

// WinCorr: corr[b,off,z,y,x] = (1/8) * sum_c x[b,c,z,y,x] * y[b,c,z+dz-1,y+dy-1,x+dx-1]
// x,y = (2,64,80,80,80) f32 ; out = (2,27,80,80,80) f32

#define B_  2
#define C_  64
#define D_  80
#define H_  80
#define W_  80

#define TZ  4
#define TY  8
#define TXB 16
#define TX  4
#define NTH 128

#define SMZ 6
#define SMY 10
#define SMXV 18          // valid columns
#define SMX 48           // padded stride: ty*48 mod 32 alternates 0/16 -> conflict-free LDS.128
#define NSTAGE (SMZ*SMY*SMXV)            // 1080
#define STAGES 3
#define BUFBYTES (SMZ*SMY*SMX*4)         // 11520

typedef unsigned long long u64;

__device__ __forceinline__ uint32_t smem_u32(const void* p) {
    return (uint32_t)__cvta_generic_to_shared(p);
}
__device__ __forceinline__ void cp_async4(uint32_t saddr, const void* gaddr, uint32_t srcsz) {
    asm volatile("cp.async.ca.shared.global [%0], [%1], 4, %2;\n"
                 :: "r"(saddr), "l"(gaddr), "r"(srcsz) : "memory");
}
__device__ __forceinline__ void cp_commit() {
    asm volatile("cp.async.commit_group;\n" ::: "memory");
}
template<int N> __device__ __forceinline__ void cp_wait() {
    asm volatile("cp.async.wait_group %0;\n" :: "n"(N) : "memory");
}
__device__ __forceinline__ void ffma2(u64& acc, u64 a, u64 b) {
    asm("fma.rn.f32x2 %0, %1, %2, %0;" : "+l"(acc) : "l"(a), "l"(b));
}
__device__ __forceinline__ u64 packf2(float lo, float hi) {
    u64 r; asm("mov.b64 %0, {%1, %2};" : "=l"(r) : "f"(lo), "f"(hi)); return r;
}
__device__ __forceinline__ float2 unpackf2(u64 v) {
    float2 r; asm("mov.b64 {%0, %1}, %2;" : "=f"(r.x), "=f"(r.y) : "l"(v)); return r;
}

__global__ void __launch_bounds__(NTH, 3)
wincorr_kernel(const float* __restrict__ x,
               const float* __restrict__ y,
               float* __restrict__ out)
{
    // ---- decode block -> (b, z0, y0, x0) ----
    int bid = blockIdx.x;
    int bx = bid % (W_ / TXB); bid /= (W_ / TXB);
    int by = bid % (H_ / TY);  bid /= (H_ / TY);
    int bz = bid % (D_ / TZ);  bid /= (D_ / TZ);
    int b  = bid;
    const int z0 = bz * TZ, y0 = by * TY, x0 = bx * TXB;

    const int tid = threadIdx.x;
    const int tx = tid & 3;
    const int ty = (tid >> 2) & 7;
    const int tz = tid >> 5;

    __shared__ float sm[STAGES][SMZ][SMY][SMX];

    const int plane = H_ * W_;       // 6400
    const int vol   = D_ * plane;    // 512000
    const uint32_t volbytes = (uint32_t)vol * 4u;

    const float* xb = x + (size_t)b * C_ * vol;
    const float* yb = y + (size_t)b * C_ * vol;
    const char*  ybc = (const char*)yb;

    // ---- precompute staging slots (channel-invariant); bit31 of goff = invalid ----
    uint32_t sadr[9];   // smem byte address (stage 0)
    uint32_t goff[9];   // byte offset into yb (clamped) | invalid<<31
#pragma unroll
    for (int k = 0; k < 9; k++) {
        int i = tid + k * NTH;
        int ii = (i < NSTAGE) ? i : 0;
        int lx = ii % SMXV;
        int t  = ii / SMXV;
        int ly = t % SMY;
        int lz = t / SMY;
        int gz = z0 - 1 + lz, gy = y0 - 1 + ly, gx = x0 - 1 + lx;
        bool inb = ((unsigned)gz < (unsigned)D_) &&
                   ((unsigned)gy < (unsigned)H_) &&
                   ((unsigned)gx < (unsigned)W_);
        int cz = min(max(gz, 0), D_ - 1);
        int cy = min(max(gy, 0), H_ - 1);
        int cx = min(max(gx, 0), W_ - 1);
        goff[k] = (uint32_t)((cz * plane + cy * W_ + cx) * 4) | (inb ? 0u : 0x80000000u);
        sadr[k] = smem_u32(&sm[0][lz][ly][lx]);
    }

    u64 acc01[27], acc23[27];
#pragma unroll
    for (int o = 0; o < 27; o++) { acc01[o] = 0ull; acc23[o] = 0ull; }

    const float* xp = xb + (size_t)(z0 + tz) * plane + (y0 + ty) * W_ + x0 + tx * TX;

    // ---- prologue: stage channels 0 and 1 ----
#pragma unroll
    for (int s = 0; s < STAGES - 1; s++) {
        const uint32_t cb = (uint32_t)s * volbytes;
        const uint32_t bo = (uint32_t)s * BUFBYTES;
#pragma unroll
        for (int k = 0; k < 9; k++) {
            if (tid + k * NTH < NSTAGE) {
                uint32_t g = goff[k];
                cp_async4(sadr[k] + bo, ybc + ((g & 0x7fffffffu) + cb),
                          (g >> 31) ? 0u : 4u);
            }
        }
        cp_commit();
    }

    float4 xv = *(const float4*)xp;

    for (int c = 0; c < C_; c++) {
        // drain: make stage c complete (stage c+1 may remain in flight)
        if (c == C_ - 1) cp_wait<0>(); else cp_wait<1>();
        __syncthreads();    // stage c visible to all; buffer (c+2)%3 reads finished (iter c-1)

        // issue stage c+2 into buffer (c+2)%STAGES
        if (c + 2 < C_) {
            const uint32_t cb = (uint32_t)(c + 2) * volbytes;
            const uint32_t bo = (uint32_t)((c + 2) % STAGES) * BUFBYTES;
#pragma unroll
            for (int k = 0; k < 9; k++) {
                if (tid + k * NTH < NSTAGE) {
                    uint32_t g = goff[k];
                    cp_async4(sadr[k] + bo, ybc + ((g & 0x7fffffffu) + cb),
                              (g >> 31) ? 0u : 4u);
                }
            }
            cp_commit();
        }

        // prefetch x for c+1 (covered by the 54 FFMA2 below)
        float4 xnext;
        if (c + 1 < C_) xnext = *(const float4*)(xp + (size_t)(c + 1) * vol);

        const u64 xa01 = packf2(xv.x, xv.y);
        const u64 xa23 = packf2(xv.z, xv.w);
        const float (*smb)[SMY][SMX] = sm[c % STAGES];

#pragma unroll
        for (int dz = 0; dz < 3; dz++) {
#pragma unroll
            for (int dy = 0; dy < 3; dy++) {
                const float* row = &smb[tz + dz][ty + dy][tx * TX];
                const float4 m  = *(const float4*)row;         // conflict-free (SMX=48)
                const float2 t2 = *(const float2*)(row + 4);
                const u64 p01 = packf2(m.x, m.y);
                const u64 p12 = packf2(m.y, m.z);
                const u64 p23 = packf2(m.z, m.w);
                const u64 p34 = packf2(m.w, t2.x);
                const u64 p45 = packf2(t2.x, t2.y);
                const int ob = dz * 9 + dy * 3;
                ffma2(acc01[ob + 0], xa01, p01);
                ffma2(acc23[ob + 0], xa23, p23);
                ffma2(acc01[ob + 1], xa01, p12);
                ffma2(acc23[ob + 1], xa23, p34);
                ffma2(acc01[ob + 2], xa01, p23);
                ffma2(acc23[ob + 2], xa23, p45);
            }
        }

        if (c + 1 < C_) xv = xnext;
    }

    // ---- epilogue: scale + streaming stores ----
    const float scale = 0.125f;
    const size_t sp = (size_t)(z0 + tz) * plane + (size_t)(y0 + ty) * W_ + (x0 + tx * TX);
    float* outb = out + (size_t)b * 27 * vol + sp;
#pragma unroll
    for (int off = 0; off < 27; off++) {
        float2 a = unpackf2(acc01[off]);
        float2 bq = unpackf2(acc23[off]);
        float4 o;
        o.x = a.x * scale;
        o.y = a.y * scale;
        o.z = bq.x * scale;
        o.w = bq.y * scale;
        __stcs((float4*)(outb + (size_t)off * vol), o);
    }
}

extern "C" void kernel_launch(void* const* d_in, const int* in_sizes, int n_in,
                              void* d_out, int out_size)
{
    const float* x = (const float*)d_in[0];
    const float* y = (const float*)d_in[1];
    float* out = (float*)d_out;

    const int nblocks = B_ * (D_ / TZ) * (H_ / TY) * (W_ / TXB); // 2000
    wincorr_kernel<<<nblocks, NTH>>>(x, y, out);
}